// round 15
// baseline (speedup 1.0000x reference)
#include <cuda_runtime.h>
#include <cuda_fp16.h>

#define NB 8
#define NN 1024
#define NF 128
#define NH 8

// -------- scratch (device globals; allocation is forbidden) --------
__device__ __half    g_Q[NB*NN*NF];      // [b*N+q][128], pre-scaled by log2e/4
// K/V in mma-fragment order: [b][kt(64)][h(8)][lane(32)][slot(4)] u32
__device__ unsigned  g_K[NB*NN*64];
__device__ unsigned  g_V[NB*NN*64];
// expanded masks in fragment order: [mb=b*16+qt][kt(64)][fp(2)][lane(32)] uint4
// fp = q-half; x/y = f=2fp (klo/khi), z/w = f=2fp+1. byte = 0x3C keep / 0x00 mask
__device__ uint4     g_emask[NB*16*64*2*32];

#define QSCALE 0.3606737602222409f   // log2(e)/4
#define ONES2  0x3C003C00u           // half2(1,1)

// attn smem layout (bytes)
#define SM_WOS   0        // Wos[128][136] half   = 34816
#define SM_XS    34816    // Xs[64][136]  half    = 17408
#define SM_BS    52224    // bs[128] float        = 512
#define SM_TOT   52736

// -------- helpers --------
static __device__ __forceinline__ float rcpf(float x){ float r; asm("rcp.approx.ftz.f32 %0,%1;":"=f"(r):"f"(x)); return r; }
static __device__ __forceinline__ unsigned h2(float a,float b){
    __half2 h = __floats2half2_rn(a,b); return *reinterpret_cast<unsigned*>(&h); }
static __device__ __forceinline__ unsigned hex2(unsigned x){
    unsigned r; asm("ex2.approx.f16x2 %0,%1;":"=r"(r):"r"(x)); return r; }
static __device__ __forceinline__ unsigned hmul2(unsigned x, unsigned y){
    unsigned r; asm("mul.f16x2 %0,%1,%2;":"=r"(r):"r"(x),"r"(y)); return r; }
static __device__ __forceinline__ unsigned prmtc(unsigned a, unsigned ctrl){
    unsigned r; asm("prmt.b32 %0,%1,%2,%3;":"=r"(r):"r"(a),"r"(0u),"r"(ctrl)); return r; }
static __device__ __forceinline__ void mma16816(float c[4], const unsigned a[4], unsigned b0, unsigned b1){
    asm volatile("mma.sync.aligned.m16n8k16.row.col.f32.f16.f16.f32 "
                 "{%0,%1,%2,%3},{%4,%5,%6,%7},{%8,%9},{%0,%1,%2,%3};"
                 : "+f"(c[0]),"+f"(c[1]),"+f"(c[2]),"+f"(c[3])
                 : "r"(a[0]),"r"(a[1]),"r"(a[2]),"r"(a[3]),"r"(b0),"r"(b1));
}
static __device__ __forceinline__ void mma16816h(unsigned &d0, unsigned &d1,
        const unsigned a[4], unsigned b0, unsigned b1){
    asm volatile("mma.sync.aligned.m16n8k16.row.col.f16.f16.f16.f16 "
                 "{%0,%1},{%2,%3,%4,%5},{%6,%7},{%8,%8};"
                 : "=r"(d0),"=r"(d1)
                 : "r"(a[0]),"r"(a[1]),"r"(a[2]),"r"(a[3]),"r"(b0),"r"(b1),"r"(0u));
}

// ============ kernel 1: fused mask compaction+expansion + Q/K/V projections ============
// blocks 0..127: mask ballot + fragment-order fp16-byte expansion; block = (b, qt)  [heavy, first]
// blocks 128..319: GEMM (mode: 0=Q,1=K,2=V frag), 128x128 tile
__global__ __launch_bounds__(512) void pre_kernel(const float* __restrict__ X,
        const float* __restrict__ A,
        const float* __restrict__ Wq, const float* __restrict__ bq,
        const float* __restrict__ Wk, const float* __restrict__ bk,
        const float* __restrict__ Wv, const float* __restrict__ bv){
    int bid = blockIdx.x;
    int tid = threadIdx.x;
    int w = tid >> 5, lane = tid & 31;
    extern __shared__ char smem[];

    if (bid < 128){
        // ---- mask block: (b, qt) covers 64 q-rows x 1024 keys ----
        int mb = bid;                      // 0..127
        int b = mb >> 4, qt = mb & 15;
        unsigned (*sb)[33] = (unsigned(*)[33])smem;   // ballots [64][33]

        #pragma unroll
        for (int rnd = 0; rnd < 4; ++rnd){
            int rr = rnd*16 + w;
            const float* a = A + ((size_t)((b<<10) + (qt<<6) + rr))*NN;
            unsigned myw = 0;
            #pragma unroll
            for (int j = 0; j < 32; ++j){
                unsigned m = __ballot_sync(0xffffffffu, a[j*32 + lane] > 0.0f);
                if (lane == j) myw = m;
            }
            sb[rr][lane] = myw;
        }
        __syncthreads();

        #pragma unroll
        for (int p = 0; p < 8; ++p){
            int idx = p*512 + tid;
            int kt = idx >> 6, fp = (idx >> 5) & 1, ln = idx & 31;
            int qr2 = ln >> 2, lc2 = ln & 3;
            int s = ((kt & 1) << 4) + 2*lc2;
            int col = kt >> 1;
            uint4 ev;
            {
                unsigned wl = sb[fp*32 + qr2][col];
                unsigned wh = sb[fp*32 + 8 + qr2][col];
                unsigned blo = (wl >> s) & 3u, bhi = (wh >> s) & 3u;
                unsigned m = blo*0x4080u | ((bhi*0x4080u) << 16);
                ev.x = prmtc(m, 0xBA98u) & 0x3C3C3C3Cu;
                blo = (wl >> (s+8)) & 3u; bhi = (wh >> (s+8)) & 3u;
                m = blo*0x4080u | ((bhi*0x4080u) << 16);
                ev.y = prmtc(m, 0xBA98u) & 0x3C3C3C3Cu;
            }
            {
                unsigned wl = sb[fp*32 + 16 + qr2][col];
                unsigned wh = sb[fp*32 + 24 + qr2][col];
                unsigned blo = (wl >> s) & 3u, bhi = (wh >> s) & 3u;
                unsigned m = blo*0x4080u | ((bhi*0x4080u) << 16);
                ev.z = prmtc(m, 0xBA98u) & 0x3C3C3C3Cu;
                blo = (wl >> (s+8)) & 3u; bhi = (wh >> (s+8)) & 3u;
                m = blo*0x4080u | ((bhi*0x4080u) << 16);
                ev.w = prmtc(m, 0xBA98u) & 0x3C3C3C3Cu;
            }
            g_emask[((size_t)(mb*64 + kt)*2 + fp)*32 + ln] = ev;
        }
        return;
    }

    // ---- GEMM part ----
    __half (*Xs)[136] = (__half(*)[136])smem;
    __half (*Ws)[136] = (__half(*)[136])(smem + 34816);
    float*  bs        = (float*)(smem + 69632);

    int gb = bid - 128;
    int mode = gb >> 6;        // 0=Q 1=K 2=V
    int tile = gb & 63;
    const float* Wp = (mode == 0) ? Wq : (mode == 1) ? Wk : Wv;
    const float* bp = (mode == 0) ? bq : (mode == 1) ? bk : bv;
    int row0 = tile * 128;

    for (int i = tid; i < 4096; i += 512){
        int r = i >> 5, c4 = (i & 31) * 4;
        float4 v = *(const float4*)&X[(size_t)(row0 + r)*NF + c4];
        uint2 u; u.x = h2(v.x, v.y); u.y = h2(v.z, v.w);
        *(uint2*)&Xs[r][c4] = u;
        float4 ww = *(const float4*)&Wp[(size_t)r*NF + c4];
        uint2 uw; uw.x = h2(ww.x, ww.y); uw.y = h2(ww.z, ww.w);
        *(uint2*)&Ws[r][c4] = uw;
    }
    if (tid < 128) bs[tid] = bp[tid];
    __syncthreads();

    int qr = lane >> 2, lc = lane & 3, ms = lc * 2;
    int rg = w >> 1, ch = w & 1;

    const unsigned* Ab = (mode == 2) ? (const unsigned*)Ws : (const unsigned*)Xs;
    const unsigned* Bb = (mode == 2) ? (const unsigned*)Xs : (const unsigned*)Ws;

    unsigned a[8][4];
    {
        const unsigned* p = Ab + (16*rg + qr)*68 + lc;
        #pragma unroll
        for (int kt = 0; kt < 8; ++kt){
            a[kt][0] = p[kt*8];
            a[kt][1] = p[kt*8 + 8*68];
            a[kt][2] = p[kt*8 + 4];
            a[kt][3] = p[kt*8 + 8*68 + 4];
        }
    }

    float c[8][4];
    #pragma unroll
    for (int j = 0; j < 8; ++j){ c[j][0]=0.f; c[j][1]=0.f; c[j][2]=0.f; c[j][3]=0.f; }
    #pragma unroll
    for (int j = 0; j < 8; ++j){
        const unsigned* bpq = Bb + (64*ch + 8*j + qr)*68 + lc;
        #pragma unroll
        for (int kt = 0; kt < 8; ++kt)
            mma16816(c[j], a[kt], bpq[kt*8], bpq[kt*8 + 4]);
    }

    int b = row0 >> 10, q0 = row0 & (NN - 1);
    #pragma unroll
    for (int j = 0; j < 8; ++j){
        if (mode == 2){
            int o0 = 16*rg + qr, o1 = o0 + 8;
            int kt = (q0 >> 4) + 4*ch + (j >> 1);
            float bo0 = bs[o0], bo1 = bs[o1];
            unsigned* basep = g_V + ((((b<<6) + kt)<<3) + rg)*128 + (qr*4 + (ms>>1))*4;
            basep[(j&1)]     = h2(c[j][0]+bo0, c[j][1]+bo0);
            basep[2 + (j&1)] = h2(c[j][2]+bo1, c[j][3]+bo1);
        } else {
            int col = 64*ch + 8*j + ms;
            float b0 = bs[col], b1 = bs[col + 1];
            if (mode == 0){
                int r = row0 + 16*rg + qr;
                *(unsigned*)&g_Q[(size_t)r*NF + col]     = h2((c[j][0]+b0)*QSCALE, (c[j][1]+b1)*QSCALE);
                *(unsigned*)&g_Q[(size_t)(r+8)*NF + col] = h2((c[j][2]+b0)*QSCALE, (c[j][3]+b1)*QSCALE);
            } else {
                int hh = 4*ch + (j >> 1);
                int kt = (q0 >> 4) + rg;
                unsigned* basep = g_K + ((((b<<6) + kt)<<3) + hh)*128 + (qr*4 + (ms>>1))*4;
                basep[(j&1)]     = h2(c[j][0]+b0, c[j][1]+b1);
                basep[2 + (j&1)] = h2(c[j][2]+b0, c[j][3]+b1);
            }
        }
    }
}

// ============ kernel 2: masked flash attention + fused output projection ============
// grid 128 (b, q0-tile of 64), 512 threads: warp = (half, head); half = q-half = emask fp
// warp: 32 query rows (2 fragments), ALL 64 key tiles, K/V/mask fragment-order gmem,
// depth-2 register prefetch, no mainloop barriers, direct normalize epilogue.
__global__ __launch_bounds__(512) void attn_kernel(const float* __restrict__ Wo,
        const float* __restrict__ bo, float* __restrict__ out){
    extern __shared__ char smem[];
    __half   (*Wos)[136]  = (__half(*)[136])(smem + SM_WOS);
    __half   (*Xs)[136]   = (__half(*)[136])(smem + SM_XS);
    float*    bs          = (float*)(smem + SM_BS);

    int tid = threadIdx.x;
    int b  = blockIdx.x >> 4;
    int qt = blockIdx.x & 15;
    int q0 = qt * 64;
    int wid = tid >> 5, lane = tid & 31;
    int h = wid & 7, half = wid >> 3;

    // stage Wo (fp32->fp16), bias
    for (int i = tid; i < 4096; i += 512){
        int r = i >> 5, c4 = (i & 31) * 4;
        float4 v = *(const float4*)&Wo[(size_t)r*NF + c4];
        uint2 u; u.x = h2(v.x, v.y); u.y = h2(v.z, v.w);
        *(uint2*)&Wos[r][c4] = u;
    }
    if (tid < 128) bs[tid] = bo[tid];

    int qr = lane >> 2;
    int lc = lane & 3;
    int ms = lc * 2;
    int rbase = 32*half;

    // Q fragments: 2 (32 query rows) for this head
    unsigned a[2][4];
    #pragma unroll
    for (int f=0; f<2; ++f){
        const __half* Qp = g_Q + (((size_t)((b<<10) + q0 + rbase + f*16 + qr)) << 7) + h*16;
        a[f][0] = *(const unsigned*)(Qp + ms);
        a[f][2] = *(const unsigned*)(Qp + ms + 8);
        const __half* Qp8 = Qp + (8 << 7);
        a[f][1] = *(const unsigned*)(Qp8 + ms);
        a[f][3] = *(const unsigned*)(Qp8 + ms + 8);
    }

    float o[2][2][4];
    float lsum[2][4];
    #pragma unroll
    for (int f=0;f<2;++f){
        #pragma unroll
        for (int j=0;j<4;++j) lsum[f][j]=0.f;
        #pragma unroll
        for (int t=0;t<2;++t){ o[f][t][0]=0.f;o[f][t][1]=0.f;o[f][t][2]=0.f;o[f][t][3]=0.f; }
    }

    // fragment pointers (units: uint4). K/V index = ((b*64+kt)*8+h)*32+lane
    //   -> base (kt=0) = b*16384 + h*32 + lane ; per-kt stride = 256
    const uint4* Kp  = ((const uint4*)g_K) + ((size_t)b<<14) + (h<<5) + lane;
    const uint4* Vp  = ((const uint4*)g_V) + ((size_t)b<<14) + (h<<5) + lane;
    // emask index = ((mb*64+kt)*2+half)*32+lane -> base = mb*4096 + half*32 + lane ; stride 64
    const uint4* EMp = g_emask + ((size_t)(b*16 + qt)<<12) + (half<<5) + lane;

    // depth-2 double-buffered prefetch
    uint4 kr[2], vr[2], er[2];
    kr[0] = Kp[0];   vr[0] = Vp[0];   er[0] = EMp[0];
    kr[1] = Kp[256]; vr[1] = Vp[256]; er[1] = EMp[64];

    #pragma unroll 2
    for (int kt = 0; kt < 64; ++kt){
        int bi = kt & 1;
        uint4 ka = kr[bi], va = vr[bi], ea = er[bi];
        if (kt < 62){
            kr[bi] = Kp[(size_t)(kt+2)*256];
            vr[bi] = Vp[(size_t)(kt+2)*256];
            er[bi] = EMp[(size_t)(kt+2)*64];
        }
        #pragma unroll
        for (int f=0; f<2; ++f){
            unsigned ex = f ? ea.z : ea.x;
            unsigned ey = f ? ea.w : ea.y;
            unsigned d0, d1, d2, d3;
            mma16816h(d0, d1, a[f], ka.x, ka.y);
            mma16816h(d2, d3, a[f], ka.z, ka.w);
            unsigned ap[4];
            ap[0] = hmul2(hex2(d0), prmtc(ex, 0x1404u));
            ap[1] = hmul2(hex2(d1), prmtc(ex, 0x3424u));
            ap[2] = hmul2(hex2(d2), prmtc(ey, 0x1404u));
            ap[3] = hmul2(hex2(d3), prmtc(ey, 0x3424u));
            mma16816(o[f][0], ap, va.x, va.y);
            mma16816(o[f][1], ap, va.z, va.w);
            mma16816(lsum[f], ap, ONES2, ONES2);
        }
    }

    // normalize and stage attn output tile (fp16) to smem — no cross-warp combine needed
    #pragma unroll
    for (int f=0; f<2; ++f){
        float inv0 = rcpf(lsum[f][0]);
        float inv1 = rcpf(lsum[f][2]);
        #pragma unroll
        for (int t=0; t<2; ++t){
            *(unsigned*)&Xs[rbase + f*16 + qr][h*16 + t*8 + ms]     = h2(o[f][t][0]*inv0, o[f][t][1]*inv0);
            *(unsigned*)&Xs[rbase + f*16 + 8 + qr][h*16 + t*8 + ms] = h2(o[f][t][2]*inv1, o[f][t][3]*inv1);
        }
    }
    __syncthreads();

    // ---- fused output projection: out(64x128) = Xs @ Wos^T + bo ----
    int rg = wid >> 2, cq = wid & 3;
    unsigned a2[8][4];
    {
        const unsigned* p = (const unsigned*)Xs + (16*rg + qr)*68 + lc;
        #pragma unroll
        for (int kt = 0; kt < 8; ++kt){
            a2[kt][0] = p[kt*8];
            a2[kt][1] = p[kt*8 + 8*68];
            a2[kt][2] = p[kt*8 + 4];
            a2[kt][3] = p[kt*8 + 8*68 + 4];
        }
    }
    #pragma unroll
    for (int j = 0; j < 4; ++j){
        float c[4] = {0.f,0.f,0.f,0.f};
        const unsigned* bp = (const unsigned*)Wos + (32*cq + 8*j + qr)*68 + lc;
        #pragma unroll
        for (int kt = 0; kt < 8; ++kt)
            mma16816(c, a2[kt], bp[kt*8], bp[kt*8 + 4]);
        int col = 32*cq + 8*j + ms;
        float b0 = bs[col], b1 = bs[col + 1];
        int r = (b<<10) + q0 + 16*rg + qr;
        *(float2*)&out[(size_t)r*NF + col]     = make_float2(c[0]+b0, c[1]+b1);
        *(float2*)&out[(size_t)(r+8)*NF + col] = make_float2(c[2]+b0, c[3]+b1);
    }
}

// -------- launcher --------
extern "C" void kernel_launch(void* const* d_in, const int* in_sizes, int n_in,
                              void* d_out, int out_size){
    const float* X  = (const float*)d_in[0];
    const float* A  = (const float*)d_in[1];
    const float* Wq = (const float*)d_in[2];
    const float* bq = (const float*)d_in[3];
    const float* Wk = (const float*)d_in[4];
    const float* bk = (const float*)d_in[5];
    const float* Wv = (const float*)d_in[6];
    const float* bv = (const float*)d_in[7];
    const float* Wo = (const float*)d_in[8];
    const float* bo = (const float*)d_in[9];
    float* out = (float*)d_out;

    const int SMEM1 = 70144;
    cudaFuncSetAttribute(pre_kernel,  cudaFuncAttributeMaxDynamicSharedMemorySize, SMEM1);
    cudaFuncSetAttribute(attn_kernel, cudaFuncAttributeMaxDynamicSharedMemorySize, SM_TOT);

    pre_kernel<<<320, 512, SMEM1>>>(X, A, Wq, bq, Wk, bk, Wv, bv);
    attn_kernel<<<128, 512, SM_TOT>>>(Wo, bo, out);
}

// round 16
// speedup vs baseline: 1.0763x; 1.0763x over previous
#include <cuda_runtime.h>
#include <cuda_fp16.h>

#define NB 8
#define NN 1024
#define NF 128
#define NH 8

// -------- scratch (device globals; allocation is forbidden) --------
__device__ __half    g_Q[NB*NN*NF];      // [b*N+q][128], pre-scaled by log2e/4
// K/V in mma-fragment order: [b][kt(64)][h(8)][lane(32)][slot(4)] u32
__device__ unsigned  g_K[NB*NN*64];
__device__ unsigned  g_V[NB*NN*64];
// expanded masks in fragment order: [mb=b*16+qt][kt(64)][fp(2)][lane(32)] uint4
// fp = q-half; x/y = f=2fp (klo/khi), z/w = f=2fp+1. byte = 0x3C keep / 0x00 mask
__device__ uint4     g_emask[NB*16*64*2*32];

#define QSCALE 0.3606737602222409f   // log2(e)/4
#define ONES2  0x3C003C00u           // half2(1,1)

// attn smem layout (bytes)
#define SM_WOS   0        // Wos[128][136] half   = 34816
#define SM_XS    34816    // Xs[64][136]  half    = 17408
#define SM_BS    52224    // bs[128] float        = 512
#define SM_TOT   52736

// -------- helpers --------
static __device__ __forceinline__ float rcpf(float x){ float r; asm("rcp.approx.ftz.f32 %0,%1;":"=f"(r):"f"(x)); return r; }
static __device__ __forceinline__ unsigned h2(float a,float b){
    __half2 h = __floats2half2_rn(a,b); return *reinterpret_cast<unsigned*>(&h); }
static __device__ __forceinline__ unsigned hex2(unsigned x){
    unsigned r; asm("ex2.approx.f16x2 %0,%1;":"=r"(r):"r"(x)); return r; }
static __device__ __forceinline__ unsigned hmul2(unsigned x, unsigned y){
    unsigned r; asm("mul.f16x2 %0,%1,%2;":"=r"(r):"r"(x),"r"(y)); return r; }
static __device__ __forceinline__ unsigned prmtc(unsigned a, unsigned ctrl){
    unsigned r; asm("prmt.b32 %0,%1,%2,%3;":"=r"(r):"r"(a),"r"(0u),"r"(ctrl)); return r; }
static __device__ __forceinline__ void mma16816(float c[4], const unsigned a[4], unsigned b0, unsigned b1){
    asm volatile("mma.sync.aligned.m16n8k16.row.col.f32.f16.f16.f32 "
                 "{%0,%1,%2,%3},{%4,%5,%6,%7},{%8,%9},{%0,%1,%2,%3};"
                 : "+f"(c[0]),"+f"(c[1]),"+f"(c[2]),"+f"(c[3])
                 : "r"(a[0]),"r"(a[1]),"r"(a[2]),"r"(a[3]),"r"(b0),"r"(b1));
}
static __device__ __forceinline__ void mma16816h(unsigned &d0, unsigned &d1,
        const unsigned a[4], unsigned b0, unsigned b1){
    asm volatile("mma.sync.aligned.m16n8k16.row.col.f16.f16.f16.f16 "
                 "{%0,%1},{%2,%3,%4,%5},{%6,%7},{%8,%8};"
                 : "=r"(d0),"=r"(d1)
                 : "r"(a[0]),"r"(a[1]),"r"(a[2]),"r"(a[3]),"r"(b0),"r"(b1),"r"(0u));
}

// ============ kernel 1: fused mask compaction+expansion + Q/K/V projections ============
// blocks 0..127: mask ballot + fragment-order fp16-byte expansion; block = (b, qt)  [heavy, first]
// blocks 128..319: GEMM (mode: 0=Q,1=K,2=V frag), 128x128 tile
__global__ __launch_bounds__(512) void pre_kernel(const float* __restrict__ X,
        const float* __restrict__ A,
        const float* __restrict__ Wq, const float* __restrict__ bq,
        const float* __restrict__ Wk, const float* __restrict__ bk,
        const float* __restrict__ Wv, const float* __restrict__ bv){
    int bid = blockIdx.x;
    int tid = threadIdx.x;
    int w = tid >> 5, lane = tid & 31;
    extern __shared__ char smem[];

    if (bid < 128){
        // ---- mask block: (b, qt) covers 64 q-rows x 1024 keys ----
        int mb = bid;                      // 0..127
        int b = mb >> 4, qt = mb & 15;
        unsigned (*sb)[33] = (unsigned(*)[33])smem;   // ballots [64][33]

        #pragma unroll
        for (int rnd = 0; rnd < 4; ++rnd){
            int rr = rnd*16 + w;
            const float* a = A + ((size_t)((b<<10) + (qt<<6) + rr))*NN;
            unsigned myw = 0;
            #pragma unroll
            for (int j = 0; j < 32; ++j){
                unsigned m = __ballot_sync(0xffffffffu, a[j*32 + lane] > 0.0f);
                if (lane == j) myw = m;
            }
            sb[rr][lane] = myw;
        }
        __syncthreads();

        #pragma unroll
        for (int p = 0; p < 8; ++p){
            int idx = p*512 + tid;
            int kt = idx >> 6, fp = (idx >> 5) & 1, ln = idx & 31;
            int qr2 = ln >> 2, lc2 = ln & 3;
            int s = ((kt & 1) << 4) + 2*lc2;
            int col = kt >> 1;
            uint4 ev;
            {
                unsigned wl = sb[fp*32 + qr2][col];
                unsigned wh = sb[fp*32 + 8 + qr2][col];
                unsigned blo = (wl >> s) & 3u, bhi = (wh >> s) & 3u;
                unsigned m = blo*0x4080u | ((bhi*0x4080u) << 16);
                ev.x = prmtc(m, 0xBA98u) & 0x3C3C3C3Cu;
                blo = (wl >> (s+8)) & 3u; bhi = (wh >> (s+8)) & 3u;
                m = blo*0x4080u | ((bhi*0x4080u) << 16);
                ev.y = prmtc(m, 0xBA98u) & 0x3C3C3C3Cu;
            }
            {
                unsigned wl = sb[fp*32 + 16 + qr2][col];
                unsigned wh = sb[fp*32 + 24 + qr2][col];
                unsigned blo = (wl >> s) & 3u, bhi = (wh >> s) & 3u;
                unsigned m = blo*0x4080u | ((bhi*0x4080u) << 16);
                ev.z = prmtc(m, 0xBA98u) & 0x3C3C3C3Cu;
                blo = (wl >> (s+8)) & 3u; bhi = (wh >> (s+8)) & 3u;
                m = blo*0x4080u | ((bhi*0x4080u) << 16);
                ev.w = prmtc(m, 0xBA98u) & 0x3C3C3C3Cu;
            }
            g_emask[((size_t)(mb*64 + kt)*2 + fp)*32 + ln] = ev;
        }
        return;
    }

    // ---- GEMM part ----
    __half (*Xs)[136] = (__half(*)[136])smem;
    __half (*Ws)[136] = (__half(*)[136])(smem + 34816);
    float*  bs        = (float*)(smem + 69632);

    int gb = bid - 128;
    int mode = gb >> 6;        // 0=Q 1=K 2=V
    int tile = gb & 63;
    const float* Wp = (mode == 0) ? Wq : (mode == 1) ? Wk : Wv;
    const float* bp = (mode == 0) ? bq : (mode == 1) ? bk : bv;
    int row0 = tile * 128;

    for (int i = tid; i < 4096; i += 512){
        int r = i >> 5, c4 = (i & 31) * 4;
        float4 v = *(const float4*)&X[(size_t)(row0 + r)*NF + c4];
        uint2 u; u.x = h2(v.x, v.y); u.y = h2(v.z, v.w);
        *(uint2*)&Xs[r][c4] = u;
        float4 ww = *(const float4*)&Wp[(size_t)r*NF + c4];
        uint2 uw; uw.x = h2(ww.x, ww.y); uw.y = h2(ww.z, ww.w);
        *(uint2*)&Ws[r][c4] = uw;
    }
    if (tid < 128) bs[tid] = bp[tid];
    __syncthreads();

    int qr = lane >> 2, lc = lane & 3, ms = lc * 2;
    int rg = w >> 1, ch = w & 1;

    const unsigned* Ab = (mode == 2) ? (const unsigned*)Ws : (const unsigned*)Xs;
    const unsigned* Bb = (mode == 2) ? (const unsigned*)Xs : (const unsigned*)Ws;

    unsigned a[8][4];
    {
        const unsigned* p = Ab + (16*rg + qr)*68 + lc;
        #pragma unroll
        for (int kt = 0; kt < 8; ++kt){
            a[kt][0] = p[kt*8];
            a[kt][1] = p[kt*8 + 8*68];
            a[kt][2] = p[kt*8 + 4];
            a[kt][3] = p[kt*8 + 8*68 + 4];
        }
    }

    float c[8][4];
    #pragma unroll
    for (int j = 0; j < 8; ++j){ c[j][0]=0.f; c[j][1]=0.f; c[j][2]=0.f; c[j][3]=0.f; }
    #pragma unroll
    for (int j = 0; j < 8; ++j){
        const unsigned* bpq = Bb + (64*ch + 8*j + qr)*68 + lc;
        #pragma unroll
        for (int kt = 0; kt < 8; ++kt)
            mma16816(c[j], a[kt], bpq[kt*8], bpq[kt*8 + 4]);
    }

    int b = row0 >> 10, q0 = row0 & (NN - 1);
    #pragma unroll
    for (int j = 0; j < 8; ++j){
        if (mode == 2){
            int o0 = 16*rg + qr, o1 = o0 + 8;
            int kt = (q0 >> 4) + 4*ch + (j >> 1);
            float bo0 = bs[o0], bo1 = bs[o1];
            unsigned* basep = g_V + ((((b<<6) + kt)<<3) + rg)*128 + (qr*4 + (ms>>1))*4;
            basep[(j&1)]     = h2(c[j][0]+bo0, c[j][1]+bo0);
            basep[2 + (j&1)] = h2(c[j][2]+bo1, c[j][3]+bo1);
        } else {
            int col = 64*ch + 8*j + ms;
            float b0 = bs[col], b1 = bs[col + 1];
            if (mode == 0){
                int r = row0 + 16*rg + qr;
                *(unsigned*)&g_Q[(size_t)r*NF + col]     = h2((c[j][0]+b0)*QSCALE, (c[j][1]+b1)*QSCALE);
                *(unsigned*)&g_Q[(size_t)(r+8)*NF + col] = h2((c[j][2]+b0)*QSCALE, (c[j][3]+b1)*QSCALE);
            } else {
                int hh = 4*ch + (j >> 1);
                int kt = (q0 >> 4) + rg;
                unsigned* basep = g_K + ((((b<<6) + kt)<<3) + hh)*128 + (qr*4 + (ms>>1))*4;
                basep[(j&1)]     = h2(c[j][0]+b0, c[j][1]+b1);
                basep[2 + (j&1)] = h2(c[j][2]+b0, c[j][3]+b1);
            }
        }
    }
}

// ============ kernel 2: masked flash attention + fused output projection ============
// grid 128 (b, q0-tile of 64), 512 threads: warp = (half, head); half = q-half = emask fp
// warp: 32 query rows (2 fragments), ALL 64 key tiles, K/V/mask fragment-order gmem,
// depth-4 register prefetch (distance ~500+ cyc > L2/DRAM latency), no mainloop barriers.
__global__ __launch_bounds__(512) void attn_kernel(const float* __restrict__ Wo,
        const float* __restrict__ bo, float* __restrict__ out){
    extern __shared__ char smem[];
    __half   (*Wos)[136]  = (__half(*)[136])(smem + SM_WOS);
    __half   (*Xs)[136]   = (__half(*)[136])(smem + SM_XS);
    float*    bs          = (float*)(smem + SM_BS);

    int tid = threadIdx.x;
    int b  = blockIdx.x >> 4;
    int qt = blockIdx.x & 15;
    int q0 = qt * 64;
    int wid = tid >> 5, lane = tid & 31;
    int h = wid & 7, half = wid >> 3;

    // stage Wo (fp32->fp16), bias
    for (int i = tid; i < 4096; i += 512){
        int r = i >> 5, c4 = (i & 31) * 4;
        float4 v = *(const float4*)&Wo[(size_t)r*NF + c4];
        uint2 u; u.x = h2(v.x, v.y); u.y = h2(v.z, v.w);
        *(uint2*)&Wos[r][c4] = u;
    }
    if (tid < 128) bs[tid] = bo[tid];

    int qr = lane >> 2;
    int lc = lane & 3;
    int ms = lc * 2;
    int rbase = 32*half;

    // Q fragments: 2 (32 query rows) for this head
    unsigned a[2][4];
    #pragma unroll
    for (int f=0; f<2; ++f){
        const __half* Qp = g_Q + (((size_t)((b<<10) + q0 + rbase + f*16 + qr)) << 7) + h*16;
        a[f][0] = *(const unsigned*)(Qp + ms);
        a[f][2] = *(const unsigned*)(Qp + ms + 8);
        const __half* Qp8 = Qp + (8 << 7);
        a[f][1] = *(const unsigned*)(Qp8 + ms);
        a[f][3] = *(const unsigned*)(Qp8 + ms + 8);
    }

    float o[2][2][4];
    float lsum[2][4];
    #pragma unroll
    for (int f=0;f<2;++f){
        #pragma unroll
        for (int j=0;j<4;++j) lsum[f][j]=0.f;
        #pragma unroll
        for (int t=0;t<2;++t){ o[f][t][0]=0.f;o[f][t][1]=0.f;o[f][t][2]=0.f;o[f][t][3]=0.f; }
    }

    // fragment pointers (units: uint4). K/V index = ((b*64+kt)*8+h)*32+lane
    //   -> base (kt=0) = b*16384 + h*32 + lane ; per-kt stride = 256
    const uint4* Kp  = ((const uint4*)g_K) + ((size_t)b<<14) + (h<<5) + lane;
    const uint4* Vp  = ((const uint4*)g_V) + ((size_t)b<<14) + (h<<5) + lane;
    // emask index = ((mb*64+kt)*2+half)*32+lane -> base = mb*4096 + half*32 + lane ; stride 64
    const uint4* EMp = g_emask + ((size_t)(b*16 + qt)<<12) + (half<<5) + lane;

    // depth-4 register prefetch
    uint4 kr[4], vr[4], er[4];
    #pragma unroll
    for (int i = 0; i < 4; ++i){
        kr[i] = Kp[(size_t)i*256];
        vr[i] = Vp[(size_t)i*256];
        er[i] = EMp[(size_t)i*64];
    }

    #pragma unroll 4
    for (int kt = 0; kt < 64; ++kt){
        int bi = kt & 3;
        uint4 ka = kr[bi], va = vr[bi], ea = er[bi];
        if (kt < 60){
            kr[bi] = Kp[(size_t)(kt+4)*256];
            vr[bi] = Vp[(size_t)(kt+4)*256];
            er[bi] = EMp[(size_t)(kt+4)*64];
        }
        #pragma unroll
        for (int f=0; f<2; ++f){
            unsigned ex = f ? ea.z : ea.x;
            unsigned ey = f ? ea.w : ea.y;
            unsigned d0, d1, d2, d3;
            mma16816h(d0, d1, a[f], ka.x, ka.y);
            mma16816h(d2, d3, a[f], ka.z, ka.w);
            unsigned ap[4];
            ap[0] = hmul2(hex2(d0), prmtc(ex, 0x1404u));
            ap[1] = hmul2(hex2(d1), prmtc(ex, 0x3424u));
            ap[2] = hmul2(hex2(d2), prmtc(ey, 0x1404u));
            ap[3] = hmul2(hex2(d3), prmtc(ey, 0x3424u));
            mma16816(o[f][0], ap, va.x, va.y);
            mma16816(o[f][1], ap, va.z, va.w);
            mma16816(lsum[f], ap, ONES2, ONES2);
        }
    }

    // normalize and stage attn output tile (fp16) to smem — no cross-warp combine needed
    #pragma unroll
    for (int f=0; f<2; ++f){
        float inv0 = rcpf(lsum[f][0]);
        float inv1 = rcpf(lsum[f][2]);
        #pragma unroll
        for (int t=0; t<2; ++t){
            *(unsigned*)&Xs[rbase + f*16 + qr][h*16 + t*8 + ms]     = h2(o[f][t][0]*inv0, o[f][t][1]*inv0);
            *(unsigned*)&Xs[rbase + f*16 + 8 + qr][h*16 + t*8 + ms] = h2(o[f][t][2]*inv1, o[f][t][3]*inv1);
        }
    }
    __syncthreads();

    // ---- fused output projection: out(64x128) = Xs @ Wos^T + bo ----
    int rg = wid >> 2, cq = wid & 3;
    unsigned a2[8][4];
    {
        const unsigned* p = (const unsigned*)Xs + (16*rg + qr)*68 + lc;
        #pragma unroll
        for (int kt = 0; kt < 8; ++kt){
            a2[kt][0] = p[kt*8];
            a2[kt][1] = p[kt*8 + 8*68];
            a2[kt][2] = p[kt*8 + 4];
            a2[kt][3] = p[kt*8 + 8*68 + 4];
        }
    }
    #pragma unroll
    for (int j = 0; j < 4; ++j){
        float c[4] = {0.f,0.f,0.f,0.f};
        const unsigned* bp = (const unsigned*)Wos + (32*cq + 8*j + qr)*68 + lc;
        #pragma unroll
        for (int kt = 0; kt < 8; ++kt)
            mma16816(c, a2[kt], bp[kt*8], bp[kt*8 + 4]);
        int col = 32*cq + 8*j + ms;
        float b0 = bs[col], b1 = bs[col + 1];
        int r = (b<<10) + q0 + 16*rg + qr;
        *(float2*)&out[(size_t)r*NF + col]     = make_float2(c[0]+b0, c[1]+b1);
        *(float2*)&out[(size_t)(r+8)*NF + col] = make_float2(c[2]+b0, c[3]+b1);
    }
}

// -------- launcher --------
extern "C" void kernel_launch(void* const* d_in, const int* in_sizes, int n_in,
                              void* d_out, int out_size){
    const float* X  = (const float*)d_in[0];
    const float* A  = (const float*)d_in[1];
    const float* Wq = (const float*)d_in[2];
    const float* bq = (const float*)d_in[3];
    const float* Wk = (const float*)d_in[4];
    const float* bk = (const float*)d_in[5];
    const float* Wv = (const float*)d_in[6];
    const float* bv = (const float*)d_in[7];
    const float* Wo = (const float*)d_in[8];
    const float* bo = (const float*)d_in[9];
    float* out = (float*)d_out;

    const int SMEM1 = 70144;
    cudaFuncSetAttribute(pre_kernel,  cudaFuncAttributeMaxDynamicSharedMemorySize, SMEM1);
    cudaFuncSetAttribute(attn_kernel, cudaFuncAttributeMaxDynamicSharedMemorySize, SM_TOT);

    pre_kernel<<<320, 512, SMEM1>>>(X, A, Wq, bq, Wk, bk, Wv, bv);
    attn_kernel<<<128, 512, SM_TOT>>>(Wo, bo, out);
}

// round 17
// speedup vs baseline: 1.1733x; 1.0901x over previous
#include <cuda_runtime.h>
#include <cuda_fp16.h>

#define NB 8
#define NN 1024
#define NF 128
#define NH 8

// -------- scratch (device globals; allocation is forbidden) --------
__device__ __half    g_Q[NB*NN*NF];      // [b*N+q][128], pre-scaled by log2e/4
// K/V in mma-fragment order: [b][kt(64)][h(8)][lane(32)][slot(4)] u32
__device__ unsigned  g_K[NB*NN*64];
__device__ unsigned  g_V[NB*NN*64];
// expanded masks in fragment order: [mb=b*16+qt][kt(64)][fp(2)][lane(32)] uint4
// fp: x/y = f=2fp (klo/khi), z/w = f=2fp+1. byte = 0x3C keep / 0x00 mask
__device__ uint4     g_emask[NB*16*64*2*32];

#define QSCALE 0.3606737602222409f   // log2(e)/4
#define ONES2  0x3C003C00u           // half2(1,1)

// attn smem layout (bytes)
#define SM_WOS   0        // Wos[128][136] half   = 34816
#define SM_XS    34816    // Xs[64][136]  half    = 17408
#define SM_BS    52224    // bs[128] float        = 512
#define SM_TOT   52736

// -------- helpers --------
static __device__ __forceinline__ float rcpf(float x){ float r; asm("rcp.approx.ftz.f32 %0,%1;":"=f"(r):"f"(x)); return r; }
static __device__ __forceinline__ unsigned h2(float a,float b){
    __half2 h = __floats2half2_rn(a,b); return *reinterpret_cast<unsigned*>(&h); }
static __device__ __forceinline__ unsigned hex2(unsigned x){
    unsigned r; asm("ex2.approx.f16x2 %0,%1;":"=r"(r):"r"(x)); return r; }
static __device__ __forceinline__ unsigned hmul2(unsigned x, unsigned y){
    unsigned r; asm("mul.f16x2 %0,%1,%2;":"=r"(r):"r"(x),"r"(y)); return r; }
static __device__ __forceinline__ unsigned prmtc(unsigned a, unsigned ctrl){
    unsigned r; asm("prmt.b32 %0,%1,%2,%3;":"=r"(r):"r"(a),"r"(0u),"r"(ctrl)); return r; }
static __device__ __forceinline__ void mma16816(float c[4], const unsigned a[4], unsigned b0, unsigned b1){
    asm volatile("mma.sync.aligned.m16n8k16.row.col.f32.f16.f16.f32 "
                 "{%0,%1,%2,%3},{%4,%5,%6,%7},{%8,%9},{%0,%1,%2,%3};"
                 : "+f"(c[0]),"+f"(c[1]),"+f"(c[2]),"+f"(c[3])
                 : "r"(a[0]),"r"(a[1]),"r"(a[2]),"r"(a[3]),"r"(b0),"r"(b1));
}
static __device__ __forceinline__ void mma16816h(unsigned &d0, unsigned &d1,
        const unsigned a[4], unsigned b0, unsigned b1){
    asm volatile("mma.sync.aligned.m16n8k16.row.col.f16.f16.f16.f16 "
                 "{%0,%1},{%2,%3,%4,%5},{%6,%7},{%8,%8};"
                 : "=r"(d0),"=r"(d1)
                 : "r"(a[0]),"r"(a[1]),"r"(a[2]),"r"(a[3]),"r"(b0),"r"(b1),"r"(0u));
}

// ============ kernel 1: fused mask compaction+expansion + Q/K/V projections ============
// blocks 0..127: mask ballot + fragment-order fp16-byte expansion; block = (b, qt)  [heavy, first]
// blocks 128..319: GEMM (mode: 0=Q,1=K,2=V frag), 128x128 tile
__global__ __launch_bounds__(512) void pre_kernel(const float* __restrict__ X,
        const float* __restrict__ A,
        const float* __restrict__ Wq, const float* __restrict__ bq,
        const float* __restrict__ Wk, const float* __restrict__ bk,
        const float* __restrict__ Wv, const float* __restrict__ bv){
    int bid = blockIdx.x;
    int tid = threadIdx.x;
    int w = tid >> 5, lane = tid & 31;
    extern __shared__ char smem[];

    if (bid < 128){
        // ---- mask block: (b, qt) covers 64 q-rows x 1024 keys ----
        int mb = bid;                      // 0..127
        int b = mb >> 4, qt = mb & 15;
        unsigned (*sb)[33] = (unsigned(*)[33])smem;   // ballots [64][33]

        #pragma unroll
        for (int rnd = 0; rnd < 4; ++rnd){
            int rr = rnd*16 + w;
            const float* a = A + ((size_t)((b<<10) + (qt<<6) + rr))*NN;
            unsigned myw = 0;
            #pragma unroll
            for (int j = 0; j < 32; ++j){
                unsigned m = __ballot_sync(0xffffffffu, a[j*32 + lane] > 0.0f);
                if (lane == j) myw = m;
            }
            sb[rr][lane] = myw;
        }
        __syncthreads();

        #pragma unroll
        for (int p = 0; p < 8; ++p){
            int idx = p*512 + tid;
            int kt = idx >> 6, fp = (idx >> 5) & 1, ln = idx & 31;
            int qr2 = ln >> 2, lc2 = ln & 3;
            int s = ((kt & 1) << 4) + 2*lc2;
            int col = kt >> 1;
            uint4 ev;
            {
                unsigned wl = sb[fp*32 + qr2][col];
                unsigned wh = sb[fp*32 + 8 + qr2][col];
                unsigned blo = (wl >> s) & 3u, bhi = (wh >> s) & 3u;
                unsigned m = blo*0x4080u | ((bhi*0x4080u) << 16);
                ev.x = prmtc(m, 0xBA98u) & 0x3C3C3C3Cu;
                blo = (wl >> (s+8)) & 3u; bhi = (wh >> (s+8)) & 3u;
                m = blo*0x4080u | ((bhi*0x4080u) << 16);
                ev.y = prmtc(m, 0xBA98u) & 0x3C3C3C3Cu;
            }
            {
                unsigned wl = sb[fp*32 + 16 + qr2][col];
                unsigned wh = sb[fp*32 + 24 + qr2][col];
                unsigned blo = (wl >> s) & 3u, bhi = (wh >> s) & 3u;
                unsigned m = blo*0x4080u | ((bhi*0x4080u) << 16);
                ev.z = prmtc(m, 0xBA98u) & 0x3C3C3C3Cu;
                blo = (wl >> (s+8)) & 3u; bhi = (wh >> (s+8)) & 3u;
                m = blo*0x4080u | ((bhi*0x4080u) << 16);
                ev.w = prmtc(m, 0xBA98u) & 0x3C3C3C3Cu;
            }
            g_emask[((size_t)(mb*64 + kt)*2 + fp)*32 + ln] = ev;
        }
        return;
    }

    // ---- GEMM part ----
    __half (*Xs)[136] = (__half(*)[136])smem;
    __half (*Ws)[136] = (__half(*)[136])(smem + 34816);
    float*  bs        = (float*)(smem + 69632);

    int gb = bid - 128;
    int mode = gb >> 6;        // 0=Q 1=K 2=V
    int tile = gb & 63;
    const float* Wp = (mode == 0) ? Wq : (mode == 1) ? Wk : Wv;
    const float* bp = (mode == 0) ? bq : (mode == 1) ? bk : bv;
    int row0 = tile * 128;

    for (int i = tid; i < 4096; i += 512){
        int r = i >> 5, c4 = (i & 31) * 4;
        float4 v = *(const float4*)&X[(size_t)(row0 + r)*NF + c4];
        uint2 u; u.x = h2(v.x, v.y); u.y = h2(v.z, v.w);
        *(uint2*)&Xs[r][c4] = u;
        float4 ww = *(const float4*)&Wp[(size_t)r*NF + c4];
        uint2 uw; uw.x = h2(ww.x, ww.y); uw.y = h2(ww.z, ww.w);
        *(uint2*)&Ws[r][c4] = uw;
    }
    if (tid < 128) bs[tid] = bp[tid];
    __syncthreads();

    int qr = lane >> 2, lc = lane & 3, ms = lc * 2;
    int rg = w >> 1, ch = w & 1;

    const unsigned* Ab = (mode == 2) ? (const unsigned*)Ws : (const unsigned*)Xs;
    const unsigned* Bb = (mode == 2) ? (const unsigned*)Xs : (const unsigned*)Ws;

    unsigned a[8][4];
    {
        const unsigned* p = Ab + (16*rg + qr)*68 + lc;
        #pragma unroll
        for (int kt = 0; kt < 8; ++kt){
            a[kt][0] = p[kt*8];
            a[kt][1] = p[kt*8 + 8*68];
            a[kt][2] = p[kt*8 + 4];
            a[kt][3] = p[kt*8 + 8*68 + 4];
        }
    }

    float c[8][4];
    #pragma unroll
    for (int j = 0; j < 8; ++j){ c[j][0]=0.f; c[j][1]=0.f; c[j][2]=0.f; c[j][3]=0.f; }
    #pragma unroll
    for (int j = 0; j < 8; ++j){
        const unsigned* bpq = Bb + (64*ch + 8*j + qr)*68 + lc;
        #pragma unroll
        for (int kt = 0; kt < 8; ++kt)
            mma16816(c[j], a[kt], bpq[kt*8], bpq[kt*8 + 4]);
    }

    int b = row0 >> 10, q0 = row0 & (NN - 1);
    #pragma unroll
    for (int j = 0; j < 8; ++j){
        if (mode == 2){
            int o0 = 16*rg + qr, o1 = o0 + 8;
            int kt = (q0 >> 4) + 4*ch + (j >> 1);
            float bo0 = bs[o0], bo1 = bs[o1];
            unsigned* basep = g_V + ((((b<<6) + kt)<<3) + rg)*128 + (qr*4 + (ms>>1))*4;
            basep[(j&1)]     = h2(c[j][0]+bo0, c[j][1]+bo0);
            basep[2 + (j&1)] = h2(c[j][2]+bo1, c[j][3]+bo1);
        } else {
            int col = 64*ch + 8*j + ms;
            float b0 = bs[col], b1 = bs[col + 1];
            if (mode == 0){
                int r = row0 + 16*rg + qr;
                *(unsigned*)&g_Q[(size_t)r*NF + col]     = h2((c[j][0]+b0)*QSCALE, (c[j][1]+b1)*QSCALE);
                *(unsigned*)&g_Q[(size_t)(r+8)*NF + col] = h2((c[j][2]+b0)*QSCALE, (c[j][3]+b1)*QSCALE);
            } else {
                int hh = 4*ch + (j >> 1);
                int kt = (q0 >> 4) + rg;
                unsigned* basep = g_K + ((((b<<6) + kt)<<3) + hh)*128 + (qr*4 + (ms>>1))*4;
                basep[(j&1)]     = h2(c[j][0]+b0, c[j][1]+b1);
                basep[2 + (j&1)] = h2(c[j][2]+b0, c[j][3]+b1);
            }
        }
    }
}

// ============ kernel 2: masked flash attention + fused output projection ============
// grid 128 (b, q0-tile of 64), 256 threads, 2 blocks/SM: warp = head (4 q-fragments,
// all 64 key tiles). K/V/mask fragment-order gmem, depth-2 prefetch, 1 barrier total.
__global__ __launch_bounds__(256, 2) void attn_kernel(const float* __restrict__ Wo,
        const float* __restrict__ bo, float* __restrict__ out){
    extern __shared__ char smem[];
    __half   (*Wos)[136]  = (__half(*)[136])(smem + SM_WOS);
    __half   (*Xs)[136]   = (__half(*)[136])(smem + SM_XS);
    float*    bs          = (float*)(smem + SM_BS);

    int tid = threadIdx.x;
    int b  = blockIdx.x >> 4;
    int qt = blockIdx.x & 15;
    int q0 = qt * 64;
    int wid = tid >> 5, lane = tid & 31;
    int h = wid;                        // warp = head

    // stage Wo (fp32->fp16), bias
    for (int i = tid; i < 4096; i += 256){
        int r = i >> 5, c4 = (i & 31) * 4;
        float4 v = *(const float4*)&Wo[(size_t)r*NF + c4];
        uint2 u; u.x = h2(v.x, v.y); u.y = h2(v.z, v.w);
        *(uint2*)&Wos[r][c4] = u;
    }
    if (tid < 128) bs[tid] = bo[tid];

    int qr = lane >> 2;
    int lc = lane & 3;
    int ms = lc * 2;

    // Q fragments: all 4 (64 query rows) for this head
    unsigned a[4][4];
    #pragma unroll
    for (int f=0; f<4; ++f){
        const __half* Qp = g_Q + (((size_t)((b<<10) + q0 + f*16 + qr)) << 7) + h*16;
        a[f][0] = *(const unsigned*)(Qp + ms);
        a[f][2] = *(const unsigned*)(Qp + ms + 8);
        const __half* Qp8 = Qp + (8 << 7);
        a[f][1] = *(const unsigned*)(Qp8 + ms);
        a[f][3] = *(const unsigned*)(Qp8 + ms + 8);
    }

    float o[4][2][4];
    float lsum[4][4];
    #pragma unroll
    for (int f=0;f<4;++f){
        #pragma unroll
        for (int j=0;j<4;++j) lsum[f][j]=0.f;
        #pragma unroll
        for (int t=0;t<2;++t){ o[f][t][0]=0.f;o[f][t][1]=0.f;o[f][t][2]=0.f;o[f][t][3]=0.f; }
    }

    // fragment pointers (units: uint4). K/V index = ((b*64+kt)*8+h)*32+lane
    //   -> base (kt=0) = b*16384 + h*32 + lane ; per-kt stride = 256
    const uint4* Kp  = ((const uint4*)g_K) + ((size_t)b<<14) + (h<<5) + lane;
    const uint4* Vp  = ((const uint4*)g_V) + ((size_t)b<<14) + (h<<5) + lane;
    // emask index = ((mb*64+kt)*2+fp)*32+lane -> base = mb*4096 ; per-kt stride = 64
    const uint4* EMp = g_emask + ((size_t)(b*16 + qt)<<12) + lane;

    // depth-2 prefetch: K, V, emask fp=0 (f0/f1) and fp=1 (f2/f3)
    uint4 kr[2], vr[2], e01r[2], e23r[2];
    #pragma unroll
    for (int i = 0; i < 2; ++i){
        kr[i]   = Kp[(size_t)i*256];
        vr[i]   = Vp[(size_t)i*256];
        e01r[i] = EMp[(size_t)i*64];
        e23r[i] = EMp[(size_t)i*64 + 32];
    }

    #pragma unroll 2
    for (int kt = 0; kt < 64; ++kt){
        int bi = kt & 1;
        uint4 ka = kr[bi], va = vr[bi], e01 = e01r[bi], e23 = e23r[bi];
        if (kt < 62){
            kr[bi]   = Kp[(size_t)(kt+2)*256];
            vr[bi]   = Vp[(size_t)(kt+2)*256];
            e01r[bi] = EMp[(size_t)(kt+2)*64];
            e23r[bi] = EMp[(size_t)(kt+2)*64 + 32];
        }
        #pragma unroll
        for (int f=0; f<4; ++f){
            unsigned ex = (f==0)?e01.x:(f==1)?e01.z:(f==2)?e23.x:e23.z;
            unsigned ey = (f==0)?e01.y:(f==1)?e01.w:(f==2)?e23.y:e23.w;
            unsigned d0, d1, d2, d3;
            mma16816h(d0, d1, a[f], ka.x, ka.y);
            mma16816h(d2, d3, a[f], ka.z, ka.w);
            unsigned ap[4];
            ap[0] = hmul2(hex2(d0), prmtc(ex, 0x1404u));
            ap[1] = hmul2(hex2(d1), prmtc(ex, 0x3424u));
            ap[2] = hmul2(hex2(d2), prmtc(ey, 0x1404u));
            ap[3] = hmul2(hex2(d3), prmtc(ey, 0x3424u));
            mma16816(o[f][0], ap, va.x, va.y);
            mma16816(o[f][1], ap, va.z, va.w);
            mma16816(lsum[f], ap, ONES2, ONES2);
        }
    }

    // normalize and stage attn output tile (fp16) to smem — warp owns its head's column
    #pragma unroll
    for (int f=0; f<4; ++f){
        int r0 = f*16 + qr, r1 = r0 + 8;
        float inv0 = rcpf(lsum[f][0]);
        float inv1 = rcpf(lsum[f][2]);
        #pragma unroll
        for (int t=0; t<2; ++t){
            *(unsigned*)&Xs[r0][h*16 + t*8 + ms] = h2(o[f][t][0]*inv0, o[f][t][1]*inv0);
            *(unsigned*)&Xs[r1][h*16 + t*8 + ms] = h2(o[f][t][2]*inv1, o[f][t][3]*inv1);
        }
    }
    __syncthreads();

    // ---- fused output projection: out(64x128) = Xs @ Wos^T + bo ----
    // 8 warps: rg = wid>>1 (16-row group), ch = wid&1 (64-col half), 8 col-groups each
    int rg = wid >> 1, ch = wid & 1;
    unsigned a2[8][4];
    {
        const unsigned* p = (const unsigned*)Xs + (16*rg + qr)*68 + lc;
        #pragma unroll
        for (int kt = 0; kt < 8; ++kt){
            a2[kt][0] = p[kt*8];
            a2[kt][1] = p[kt*8 + 8*68];
            a2[kt][2] = p[kt*8 + 4];
            a2[kt][3] = p[kt*8 + 8*68 + 4];
        }
    }
    #pragma unroll
    for (int j = 0; j < 8; ++j){
        float c[4] = {0.f,0.f,0.f,0.f};
        const unsigned* bp = (const unsigned*)Wos + (64*ch + 8*j + qr)*68 + lc;
        #pragma unroll
        for (int kt = 0; kt < 8; ++kt)
            mma16816(c, a2[kt], bp[kt*8], bp[kt*8 + 4]);
        int col = 64*ch + 8*j + ms;
        float b0 = bs[col], b1 = bs[col + 1];
        int r = (b<<10) + q0 + 16*rg + qr;
        *(float2*)&out[(size_t)r*NF + col]     = make_float2(c[0]+b0, c[1]+b1);
        *(float2*)&out[(size_t)(r+8)*NF + col] = make_float2(c[2]+b0, c[3]+b1);
    }
}

// -------- launcher --------
extern "C" void kernel_launch(void* const* d_in, const int* in_sizes, int n_in,
                              void* d_out, int out_size){
    const float* X  = (const float*)d_in[0];
    const float* A  = (const float*)d_in[1];
    const float* Wq = (const float*)d_in[2];
    const float* bq = (const float*)d_in[3];
    const float* Wk = (const float*)d_in[4];
    const float* bk = (const float*)d_in[5];
    const float* Wv = (const float*)d_in[6];
    const float* bv = (const float*)d_in[7];
    const float* Wo = (const float*)d_in[8];
    const float* bo = (const float*)d_in[9];
    float* out = (float*)d_out;

    const int SMEM1 = 70144;
    cudaFuncSetAttribute(pre_kernel,  cudaFuncAttributeMaxDynamicSharedMemorySize, SMEM1);
    cudaFuncSetAttribute(attn_kernel, cudaFuncAttributeMaxDynamicSharedMemorySize, SM_TOT);

    pre_kernel<<<320, 512, SMEM1>>>(X, A, Wq, bq, Wk, bk, Wv, bv);
    attn_kernel<<<128, 256, SM_TOT>>>(Wo, bo, out);
}